// round 6
// baseline (speedup 1.0000x reference)
#include <cuda_runtime.h>

// Shapes fixed by reference: d2 [16, 8192, 256] fp32
constexpr int B = 16, L = 8192, K4 = 64;
constexpr float LAM = 0.95f, OM = 0.05f;

constexpr int TR  = 8;              // timesteps per sub-chunk (register tile)
constexpr int GRP = 4;              // sub-chunks per CTA
constexpr int TRC = TR * GRP;       // 32 timesteps per CTA
constexpr int CPR = L / TRC;        // 256 CTAs per batch row
constexpr int NCTA = B * CPR;       // 4096
constexpr int D   = 8;              // lookback depth: (0.95^32)^8 ~ 2e-6

__device__ float4 g_aggA[NCTA * K4];  // per-CTA zero-seeded 32-step aggregate
__device__ int    g_flag[NCTA];       // epoch counters (never reset; +1 per launch)

__device__ __forceinline__ float4 f4fma(float a, float4 x, float4 y) {
    return make_float4(fmaf(a, x.x, y.x), fmaf(a, x.y, y.y),
                       fmaf(a, x.z, y.z), fmaf(a, x.w, y.w));
}
__device__ __forceinline__ float4 f4scale(float a, float4 x) {
    return make_float4(a * x.x, a * x.y, a * x.z, a * x.w);
}

__global__ __launch_bounds__(256, 4) void pft_scan(const float4* __restrict__ d2,
                                                   float4* __restrict__ out) {
    __shared__ float4 s_agg[GRP][K4];
    __shared__ float4 s_zin[K4];

    const int bid  = blockIdx.x;
    const int ct   = bid & (CPR - 1);   // chunk index within row
    const int b    = bid >> 8;          // batch row
    const int tid  = threadIdx.x;
    const int lane = tid & (K4 - 1);    // k4 lane
    const int s    = tid >> 6;          // sub-chunk 0..3

    // Epoch: own flag only ever written by this bid; read before publish.
    const int n = (tid < K4) ? g_flag[bid] : 0;

    // lam^(8*i): 1, lam^8, lam^16, lam^24
    const float PW[4] = {1.f, 0.66342043f, 0.44012667f, 0.29198906f};

    const size_t base = ((size_t)b * L + (size_t)ct * TRC + (size_t)s * TR) * K4 + lane;

    // ---- Load 8 float4 (independent, coalesced)
    float4 x[TR];
    #pragma unroll
    for (int t = 0; t < TR; ++t)
        x[t] = d2[base + (size_t)t * K4];

    // ---- Zero-seeded local scan in registers
    float4 z = make_float4(0.f, 0.f, 0.f, 0.f);
    #pragma unroll
    for (int t = 0; t < TR; ++t) {
        z.x = fmaf(LAM, z.x, OM * x[t].x);
        z.y = fmaf(LAM, z.y, OM * x[t].y);
        z.z = fmaf(LAM, z.z, OM * x[t].z);
        z.w = fmaf(LAM, z.w, OM * x[t].w);
        x[t] = z;
    }
    s_agg[s][lane] = z;
    __syncthreads();

    // ---- Combine sub-aggregates into CTA aggregate, publish epoch n+1
    if (tid < K4) {
        float4 A = s_agg[3][tid];
        A = f4fma(PW[1], s_agg[2][tid], A);
        A = f4fma(PW[2], s_agg[1][tid], A);
        A = f4fma(PW[3], s_agg[0][tid], A);
        g_aggA[bid * K4 + tid] = A;
    }
    __syncthreads();
    if (tid == 0) { __threadfence(); atomicExch(&g_flag[bid], n + 1); }

    // ---- Inter-CTA truncated lookback (depth 8, ratio lam^32)
    const int nb = (ct < D) ? ct : D;
    if (tid < K4) {
        for (int j = 1; j <= nb; ++j)
            while (((volatile int*)g_flag)[bid - j] < n + 1) __nanosleep(20);
        __threadfence();
        float4 zin = make_float4(0.f, 0.f, 0.f, 0.f);
        float w = 1.f;                       // (lam^32)^(j-1)
        for (int j = 1; j <= nb; ++j) {
            zin = f4fma(w, g_aggA[(bid - j) * K4 + tid], zin);
            w *= 0.19371148f;                // lam^32
        }
        s_zin[tid] = zin;
    }
    __syncthreads();

    // ---- Exact carry at this sub-chunk's entry
    float4 carry = f4scale(PW[s], s_zin[lane]);
    for (int i = 0; i < s; ++i)
        carry = f4fma(PW[s - 1 - i], s_agg[i][lane], carry);

    // ---- Fixup z_exact(t) = z_local(t) + carry*lam^(t+1), store
    #pragma unroll
    for (int t = 0; t < TR; ++t) {
        carry = f4scale(LAM, carry);
        x[t].x += carry.x;
        x[t].y += carry.y;
        x[t].z += carry.z;
        x[t].w += carry.w;
        out[base + (size_t)t * K4] = x[t];
    }
}

extern "C" void kernel_launch(void* const* d_in, const int* in_sizes, int n_in,
                              void* d_out, int out_size) {
    (void)in_sizes; (void)n_in; (void)out_size;
    const float4* d2 = (const float4*)d_in[0];
    float4* out = (float4*)d_out;

    pft_scan<<<NCTA, 256>>>(d2, out);
}

// round 8
// speedup vs baseline: 1.2547x; 1.2547x over previous
#include <cuda_runtime.h>

// Shapes fixed by reference: d2 [16, 8192, 256] fp32
constexpr int B = 16, L = 8192, K4 = 64;
constexpr float LAM = 0.95f, OM = 0.05f;
constexpr float L8  = 0.66342043f;   // 0.95^8
constexpr float L16 = 0.44012667f;   // 0.95^16
constexpr float L24 = 0.29198906f;   // 0.95^24
constexpr float L32 = 0.19371148f;   // 0.95^32

constexpr int TR   = 8;      // steps per thread per sub-tile
constexpr int GRP  = 4;      // groups per sub-tile (256 thr = 64 lanes x 4)
constexpr int ST   = TR * GRP;        // 32 steps per sub-tile
constexpr int SEG  = 512;             // steps per CTA segment
constexpr int NSUB = SEG / ST;        // 16 main sub-tiles
constexpr int WSUB = 6;               // warmup sub-tiles (192 steps, lam^192 ~ 5e-5)
constexpr int SEGR = L / SEG;         // 16 segments per row
constexpr int NCTA = B * SEGR;        // 256 CTAs
constexpr int IST  = ST * K4;         // float4 stride per sub-tile (2048)

__device__ __forceinline__ float4 f4fma(float a, float4 u, float4 v) {
    return make_float4(fmaf(a, u.x, v.x), fmaf(a, u.y, v.y),
                       fmaf(a, u.z, v.z), fmaf(a, u.w, v.w));
}
__device__ __forceinline__ float4 f4s(float a, float4 u) {
    return make_float4(a * u.x, a * u.y, a * u.z, a * u.w);
}

__device__ __forceinline__ void ldtile(float4 (&buf)[TR], const float4* __restrict__ p) {
#pragma unroll
    for (int t = 0; t < TR; ++t) buf[t] = p[t * K4];
}

// Scan one sub-tile: zero-seeded local scan, SMEM carry combine (exact within
// segment), optional fixup+store, update running carry C.
__device__ __forceinline__ void proc(float4 (&x)[TR], float4& C,
                                     float4 (*s_agg)[K4], int lane, int s,
                                     bool doStore, float4* __restrict__ q) {
    float4 z = make_float4(0.f, 0.f, 0.f, 0.f);
#pragma unroll
    for (int t = 0; t < TR; ++t) {
        z.x = fmaf(LAM, z.x, OM * x[t].x);
        z.y = fmaf(LAM, z.y, OM * x[t].y);
        z.z = fmaf(LAM, z.z, OM * x[t].z);
        z.w = fmaf(LAM, z.w, OM * x[t].w);
        x[t] = z;
    }
    s_agg[s][lane] = z;
    __syncthreads();
    const float4 a0 = s_agg[0][lane], a1 = s_agg[1][lane];
    const float4 a2 = s_agg[2][lane], a3 = s_agg[3][lane];

    if (doStore) {
        // exact z at this group's entry (s uniform per warp -> no divergence)
        float4 e;
        if      (s == 0) e = C;
        else if (s == 1) e = f4fma(L8,  C, a0);
        else if (s == 2) e = f4fma(L16, C, f4fma(L8, a0, a1));
        else             e = f4fma(L24, C, f4fma(L16, a0, f4fma(L8, a1, a2)));
        float4 cf = e;
#pragma unroll
        for (int t = 0; t < TR; ++t) {
            cf = f4s(LAM, cf);               // e * lam^(t+1)
            x[t].x += cf.x; x[t].y += cf.y; x[t].z += cf.z; x[t].w += cf.w;
            q[t * K4] = x[t];
        }
    }
    // running carry: C' = lam^32*C + (a3 + L8*a2 + L16*a1 + L24*a0)
    float4 Af = f4fma(L8, f4fma(L8, f4fma(L8, a0, a1), a2), a3);
    C = f4fma(L32, C, Af);
    __syncthreads();                         // protect s_agg for next sub-tile
}

__global__ __launch_bounds__(256, 2) void pft_scan(const float4* __restrict__ d2,
                                                   float4* __restrict__ out) {
    __shared__ float4 s_agg[GRP][K4];
    const int tid  = threadIdx.x;
    const int lane = tid & (K4 - 1);
    const int s    = tid >> 6;
    const int bid  = blockIdx.x;
    const int ct   = bid & (SEGR - 1);       // segment within row
    const int b    = bid >> 4;               // batch row

    const int w     = ct ? WSUB : 0;         // warmup sub-tiles
    const int niter = w + NSUB;              // 16 or 22 (both even)
    const long long g0 = (long long)ct * SEG - (long long)w * ST;

    const size_t thr0 = ((size_t)b * L + g0) * K4 + (size_t)s * TR * K4 + lane;
    const float4* p = d2  + thr0;
    float4*       q = out + thr0;

    float4 C = make_float4(0.f, 0.f, 0.f, 0.f);
    float4 bufA[TR], bufB[TR];

    ldtile(bufA, p);                          // preload sub-tile 0
    for (int i = 0; i < niter; i += 2) {
        // even iteration: prefetch i+1 into B, process A
        ldtile(bufB, p + (size_t)(i + 1) * IST);      // i+1 < niter (niter even)
        proc(bufA, C, s_agg, lane, s, i >= w, q + (size_t)i * IST);
        // odd iteration: prefetch i+2 into A, process B
        if (i + 2 < niter) ldtile(bufA, p + (size_t)(i + 2) * IST);
        proc(bufB, C, s_agg, lane, s, i + 1 >= w, q + (size_t)(i + 1) * IST);
    }
}

extern "C" void kernel_launch(void* const* d_in, const int* in_sizes, int n_in,
                              void* d_out, int out_size) {
    (void)in_sizes; (void)n_in; (void)out_size;
    const float4* d2 = (const float4*)d_in[0];
    float4* out = (float4*)d_out;

    pft_scan<<<NCTA, 256>>>(d2, out);
}